// round 1
// baseline (speedup 1.0000x reference)
#include <cuda_runtime.h>
#include <math.h>

#define N_NODES 50000
#define N_EDGES 800000
#define NFEAT   512
#define NHID    128
#define NLAYERS 16

// ---------------- scratch (device globals: no allocation allowed) ----------------
__device__ __align__(16)  int   g_deg[N_NODES];
__device__ __align__(16)  float g_dinv[N_NODES];
__device__ __align__(16)  int   g_rowptr[N_NODES + 1];
__device__ __align__(16)  int   g_fill[N_NODES];
__device__ __align__(16)  int   g_ecol[N_EDGES];
__device__ __align__(16)  float g_ew[N_EDGES];
__device__ __align__(128) float g_h0[(size_t)N_NODES * NHID];
__device__ __align__(128) float g_bufA[(size_t)N_NODES * NHID];
__device__ __align__(128) float g_bufB[(size_t)N_NODES * NHID];
__device__ __align__(128) float g_support[(size_t)N_NODES * NHID];
__device__ __align__(128) float g_wp[NLAYERS * NHID * NHID];

// ---------------- packed f32x2 helpers (sm_100+ PTX) ----------------
__device__ __forceinline__ unsigned long long fma2(unsigned long long a,
                                                   unsigned long long b,
                                                   unsigned long long c) {
    unsigned long long d;
    asm("fma.rn.f32x2 %0, %1, %2, %3;" : "=l"(d) : "l"(a), "l"(b), "l"(c));
    return d;
}
__device__ __forceinline__ unsigned long long pack2(float x) {
    unsigned long long d;
    asm("mov.b64 %0, {%1, %1};" : "=l"(d) : "f"(x));
    return d;
}
__device__ __forceinline__ float lo2(unsigned long long v) {
    return __uint_as_float((unsigned)v);
}
__device__ __forceinline__ float hi2(unsigned long long v) {
    return __uint_as_float((unsigned)(v >> 32));
}

// ---------------- preprocessing kernels ----------------
__global__ void k_init_nodes() {
    int i = blockIdx.x * blockDim.x + threadIdx.x;
    if (i < N_NODES) { g_deg[i] = 1; g_fill[i] = 0; }  // self loop counts 1
}

__global__ void k_count(const int* __restrict__ row) {
    int e = blockIdx.x * blockDim.x + threadIdx.x;
    if (e < N_EDGES) atomicAdd(&g_deg[row[e]], 1);
}

__global__ void k_dinv() {
    int i = blockIdx.x * blockDim.x + threadIdx.x;
    if (i < N_NODES) g_dinv[i] = rsqrtf((float)g_deg[i]);
}

// single-block exclusive scan of (deg-1) -> rowptr
__global__ void k_scan() {
    __shared__ int wsum[32];
    __shared__ int carry_s;
    int t = threadIdx.x, lane = t & 31, wid = t >> 5;
    if (t == 0) carry_s = 0;
    __syncthreads();
    for (int base = 0; base < N_NODES; base += 1024) {
        int i = base + t;
        int v = (i < N_NODES) ? (g_deg[i] - 1) : 0;
        int x = v;
        #pragma unroll
        for (int off = 1; off < 32; off <<= 1) {
            int y = __shfl_up_sync(0xffffffffu, x, off);
            if (lane >= off) x += y;
        }
        if (lane == 31) wsum[wid] = x;
        __syncthreads();
        if (wid == 0) {
            int w = wsum[lane];
            int xs = w;
            #pragma unroll
            for (int off = 1; off < 32; off <<= 1) {
                int y = __shfl_up_sync(0xffffffffu, xs, off);
                if (lane >= off) xs += y;
            }
            wsum[lane] = xs - w;  // exclusive warp offsets
        }
        __syncthreads();
        int incl = x + wsum[wid] + carry_s;
        if (i < N_NODES) g_rowptr[i] = incl - v;  // exclusive
        __syncthreads();
        if (t == 1023) carry_s = incl;
        __syncthreads();
    }
    if (t == 0) g_rowptr[N_NODES] = carry_s;
}

__global__ void k_fill_csr(const int* __restrict__ row, const int* __restrict__ col) {
    int e = blockIdx.x * blockDim.x + threadIdx.x;
    if (e >= N_EDGES) return;
    int r = row[e], c = col[e];
    int pos = g_rowptr[r] + atomicAdd(&g_fill[r], 1);
    g_ecol[pos] = c;
    g_ew[pos] = 0.9f * g_dinv[r] * g_dinv[c];  // (1-alpha) folded in
}

// Wp[l] = theta_l * W_l + (1-theta_l) * I
__global__ void k_wp(const float* __restrict__ cw) {
    int idx = blockIdx.x * blockDim.x + threadIdx.x;
    if (idx >= NLAYERS * NHID * NHID) return;
    int l = idx >> 14;
    int k = (idx >> 7) & 127;
    int j = idx & 127;
    float theta = logf(0.5f / (float)(l + 1) + 1.0f);
    float v = theta * cw[idx];
    if (k == j) v += 1.0f - theta;
    g_wp[idx] = v;
}

// ---------------- SpMM: support = 0.9 * (A_norm h) + 0.1 * h0 ----------------
// one warp per row, lane owns a float4 (128 feats = 32 lanes x 4)
__global__ void spmm_kernel(const float* __restrict__ hin, float* __restrict__ sup) {
    int gw = (blockIdx.x * blockDim.x + threadIdx.x) >> 5;
    if (gw >= N_NODES) return;
    int lane = threadIdx.x & 31;
    float dr = g_dinv[gw];
    float sw = 0.9f * dr * dr;  // self-loop weight * (1-alpha)
    float4 a  = ((const float4*)(hin  + (size_t)gw * NHID))[lane];
    float4 b0 = ((const float4*)(g_h0 + (size_t)gw * NHID))[lane];
    float4 acc;
    acc.x = fmaf(sw, a.x, 0.1f * b0.x);
    acc.y = fmaf(sw, a.y, 0.1f * b0.y);
    acc.z = fmaf(sw, a.z, 0.1f * b0.z);
    acc.w = fmaf(sw, a.w, 0.1f * b0.w);
    int beg = g_rowptr[gw], end = g_rowptr[gw + 1];
    #pragma unroll 4
    for (int j = beg; j < end; j++) {
        int c = g_ecol[j];
        float w = g_ew[j];
        float4 v = ((const float4*)(hin + (size_t)c * NHID))[lane];
        acc.x = fmaf(w, v.x, acc.x);
        acc.y = fmaf(w, v.y, acc.y);
        acc.z = fmaf(w, v.z, acc.z);
        acc.w = fmaf(w, v.w, acc.w);
    }
    ((float4*)(sup + (size_t)gw * NHID))[lane] = acc;
}

// ---------------- fp32 GEMM (N=128 fixed), packed f32x2 FMA ----------------
// C[M,128] = A[M,K] @ B[K,128] (+bias) (+relu). Block tile 128x128, BK=16,
// 256 threads, each thread: 8 rows x (4+4 split cols), accumulators packed.
__global__ __launch_bounds__(256, 2)
void gemm128(const float* __restrict__ A, const float* __restrict__ B,
             const float* __restrict__ bias, float* __restrict__ C,
             int M, int K, int do_relu) {
    __shared__ float As[16][132];  // k-major, padded
    __shared__ float Bs[16][128];
    const int tid = threadIdx.x;
    const int tx = tid & 15;       // col group
    const int ty = tid >> 4;       // row group
    const int row0 = blockIdx.x * 128;

    unsigned long long acc[8][4];
    #pragma unroll
    for (int i = 0; i < 8; i++)
        #pragma unroll
        for (int j = 0; j < 4; j++) acc[i][j] = 0ull;

    const int ar = tid >> 2;          // 0..63
    const int ak = (tid & 3) << 2;    // 0,4,8,12
    const int bk = tid >> 5;          // 0..7
    const int bc = (tid & 31) << 2;   // 0..124

    for (int k0 = 0; k0 < K; k0 += 16) {
        #pragma unroll
        for (int rep = 0; rep < 2; rep++) {
            int rr = ar + rep * 64;
            int grow = row0 + rr;
            float4 v = make_float4(0.f, 0.f, 0.f, 0.f);
            if (grow < M) v = *(const float4*)(A + (size_t)grow * K + k0 + ak);
            As[ak + 0][rr] = v.x; As[ak + 1][rr] = v.y;
            As[ak + 2][rr] = v.z; As[ak + 3][rr] = v.w;
        }
        #pragma unroll
        for (int rep = 0; rep < 2; rep++) {
            int kk = bk + rep * 8;
            *(float4*)&Bs[kk][bc] = *(const float4*)(B + (size_t)(k0 + kk) * 128 + bc);
        }
        __syncthreads();
        #pragma unroll
        for (int kk = 0; kk < 16; kk++) {
            const float4 a0 = *(const float4*)&As[kk][ty * 8];
            const float4 a1 = *(const float4*)&As[kk][ty * 8 + 4];
            const ulonglong2 bA = *(const ulonglong2*)&Bs[kk][tx * 4];
            const ulonglong2 bB = *(const ulonglong2*)&Bs[kk][64 + tx * 4];
            unsigned long long av[8];
            av[0] = pack2(a0.x); av[1] = pack2(a0.y); av[2] = pack2(a0.z); av[3] = pack2(a0.w);
            av[4] = pack2(a1.x); av[5] = pack2(a1.y); av[6] = pack2(a1.z); av[7] = pack2(a1.w);
            #pragma unroll
            for (int i = 0; i < 8; i++) {
                acc[i][0] = fma2(av[i], bA.x, acc[i][0]);
                acc[i][1] = fma2(av[i], bA.y, acc[i][1]);
                acc[i][2] = fma2(av[i], bB.x, acc[i][2]);
                acc[i][3] = fma2(av[i], bB.y, acc[i][3]);
            }
        }
        __syncthreads();
    }

    float biasA[4] = {0.f, 0.f, 0.f, 0.f};
    float biasB[4] = {0.f, 0.f, 0.f, 0.f};
    if (bias) {
        #pragma unroll
        for (int j = 0; j < 4; j++) {
            biasA[j] = bias[tx * 4 + j];
            biasB[j] = bias[64 + tx * 4 + j];
        }
    }
    #pragma unroll
    for (int i = 0; i < 8; i++) {
        int gr = row0 + ty * 8 + i;
        if (gr >= M) break;
        float o[8];
        o[0] = lo2(acc[i][0]) + biasA[0]; o[1] = hi2(acc[i][0]) + biasA[1];
        o[2] = lo2(acc[i][1]) + biasA[2]; o[3] = hi2(acc[i][1]) + biasA[3];
        o[4] = lo2(acc[i][2]) + biasB[0]; o[5] = hi2(acc[i][2]) + biasB[1];
        o[6] = lo2(acc[i][3]) + biasB[2]; o[7] = hi2(acc[i][3]) + biasB[3];
        if (do_relu) {
            #pragma unroll
            for (int j = 0; j < 8; j++) o[j] = fmaxf(o[j], 0.0f);
        }
        float4 vA = make_float4(o[0], o[1], o[2], o[3]);
        float4 vB = make_float4(o[4], o[5], o[6], o[7]);
        *(float4*)(C + (size_t)gr * 128 + tx * 4) = vA;
        *(float4*)(C + (size_t)gr * 128 + 64 + tx * 4) = vB;
    }
}

// ---------------- launch ----------------
extern "C" void kernel_launch(void* const* d_in, const int* in_sizes, int n_in,
                              void* d_out, int out_size) {
    const float* x      = (const float*)d_in[0];
    const int*   eidx   = (const int*)d_in[1];
    const float* conv_w = (const float*)d_in[2];
    const float* fc0_w  = (const float*)d_in[3];
    const float* fc0_b  = (const float*)d_in[4];
    const float* fc1_w  = (const float*)d_in[5];
    const float* fc1_b  = (const float*)d_in[6];
    float* out = (float*)d_out;
    const int* row = eidx;
    const int* col = eidx + N_EDGES;

    float *h0, *bufA, *bufB, *sup, *wp;
    cudaGetSymbolAddress((void**)&h0,   g_h0);
    cudaGetSymbolAddress((void**)&bufA, g_bufA);
    cudaGetSymbolAddress((void**)&bufB, g_bufB);
    cudaGetSymbolAddress((void**)&sup,  g_support);
    cudaGetSymbolAddress((void**)&wp,   g_wp);

    const int NB_N = (N_NODES + 255) / 256;   // 196
    const int NB_E = (N_EDGES + 255) / 256;   // 3125
    const int NB_G = (N_NODES + 127) / 128;   // 391

    k_init_nodes<<<NB_N, 256>>>();
    k_count<<<NB_E, 256>>>(row);
    k_dinv<<<NB_N, 256>>>();
    k_scan<<<1, 1024>>>();
    k_fill_csr<<<NB_E, 256>>>(row, col);
    k_wp<<<(NLAYERS * NHID * NHID) / 256, 256>>>(conv_w);

    // h0 = relu(x @ fc0_w + fc0_b)
    gemm128<<<NB_G, 256>>>(x, fc0_w, fc0_b, h0, N_NODES, NFEAT, 1);

    const float* hin = h0;
    for (int l = 0; l < NLAYERS; l++) {
        float* hout = (l & 1) ? bufB : bufA;
        spmm_kernel<<<(N_NODES * 32 + 255) / 256, 256>>>(hin, sup);
        gemm128<<<NB_G, 256>>>(sup, wp + (size_t)l * NHID * NHID, nullptr,
                               hout, N_NODES, NHID, 1);
        hin = hout;
    }

    // out = h @ fc1_w + fc1_b (no relu)
    gemm128<<<NB_G, 256>>>(hin, fc1_w, fc1_b, out, N_NODES, NHID, 0);
}

// round 3
// speedup vs baseline: 1.3280x; 1.3280x over previous
#include <cuda_runtime.h>
#include <cuda_bf16.h>
#include <math.h>
#include <stdint.h>

#define N_NODES 50000
#define N_EDGES 800000
#define NFEAT   512
#define NHID    128
#define NLAYERS 16

#define BM 128
#define BN 128
#define BK 64
// smem: per stage 4 tiles of [128 rows x 64 cols bf16] = 4 * 16KB; 2 stages = 128KB
#define STAGE_BYTES 65536
#define TILE_BYTES  16384

// ---------------- scratch (device globals) ----------------
__device__ __align__(16)  int   g_deg[N_NODES];
__device__ __align__(16)  float g_dinv[N_NODES];
__device__ __align__(16)  int   g_rowptr[N_NODES + 1];
__device__ __align__(16)  int   g_fill[N_NODES];
__device__ __align__(16)  int   g_ecol[N_EDGES];
__device__ __align__(16)  float g_ew[N_EDGES];
__device__ __align__(16)  int   g_bsum[64];

__device__ __align__(128) float g_h0[(size_t)N_NODES * NHID];
__device__ __align__(128) float g_bufA[(size_t)N_NODES * NHID];
__device__ __align__(128) float g_bufB[(size_t)N_NODES * NHID];
__device__ __align__(128) __nv_bfloat16 g_sh[(size_t)N_NODES * NHID];
__device__ __align__(128) __nv_bfloat16 g_sl[(size_t)N_NODES * NHID];
__device__ __align__(128) __nv_bfloat16 g_xh[(size_t)N_NODES * NFEAT];
__device__ __align__(128) __nv_bfloat16 g_xl[(size_t)N_NODES * NFEAT];
__device__ __align__(128) __nv_bfloat16 g_wth[NLAYERS * NHID * NHID];
__device__ __align__(128) __nv_bfloat16 g_wtl[NLAYERS * NHID * NHID];
__device__ __align__(128) __nv_bfloat16 g_f0h[NHID * NFEAT];
__device__ __align__(128) __nv_bfloat16 g_f0l[NHID * NFEAT];
__device__ __align__(128) __nv_bfloat16 g_f1h[NHID * NHID];
__device__ __align__(128) __nv_bfloat16 g_f1l[NHID * NHID];

// ---------------- PTX helpers (all baseline sm_80+: safe on sm_103 non-'a') ----------------
__device__ __forceinline__ uint32_t smem_u32(const void* p) {
    uint32_t a;
    asm("{ .reg .u64 t; cvta.to.shared.u64 t, %1; cvt.u32.u64 %0, t; }" : "=r"(a) : "l"(p));
    return a;
}
__device__ __forceinline__ void cp16(uint32_t dst, const void* src, bool valid) {
    asm volatile("cp.async.cg.shared.global [%0], [%1], 16, %2;"
                 :: "r"(dst), "l"(src), "r"(valid ? 16 : 0) : "memory");
}
__device__ __forceinline__ void cp_commit() {
    asm volatile("cp.async.commit_group;" ::: "memory");
}
__device__ __forceinline__ void cp_wait1() {
    asm volatile("cp.async.wait_group 1;" ::: "memory");
}
__device__ __forceinline__ void ldsm4(uint32_t* r, uint32_t addr) {
    asm volatile("ldmatrix.sync.aligned.m8n8.x4.shared.b16 {%0,%1,%2,%3}, [%4];"
                 : "=r"(r[0]), "=r"(r[1]), "=r"(r[2]), "=r"(r[3]) : "r"(addr));
}
__device__ __forceinline__ void mma16816(float* d, const uint32_t* a, const uint32_t* b) {
    asm volatile("mma.sync.aligned.m16n8k16.row.col.f32.bf16.bf16.f32 "
                 "{%0,%1,%2,%3}, {%4,%5,%6,%7}, {%8,%9}, {%0,%1,%2,%3};"
                 : "+f"(d[0]), "+f"(d[1]), "+f"(d[2]), "+f"(d[3])
                 : "r"(a[0]), "r"(a[1]), "r"(a[2]), "r"(a[3]), "r"(b[0]), "r"(b[1]));
}
__device__ __forceinline__ uint32_t pack_bf16(float a, float b) {
    __nv_bfloat16 ha = __float2bfloat16(a), hb = __float2bfloat16(b);
    return ((uint32_t)*(unsigned short*)&hb << 16) | *(unsigned short*)&ha;
}

// ---------------- preprocessing kernels ----------------
__global__ void k_init_nodes() {
    int i = blockIdx.x * blockDim.x + threadIdx.x;
    if (i < N_NODES) { g_deg[i] = 1; g_fill[i] = 0; }
}
__global__ void k_count(const int* __restrict__ row) {
    int e = blockIdx.x * blockDim.x + threadIdx.x;
    if (e < N_EDGES) atomicAdd(&g_deg[row[e]], 1);
}
__global__ void k_dinv() {
    int i = blockIdx.x * blockDim.x + threadIdx.x;
    if (i < N_NODES) g_dinv[i] = rsqrtf((float)g_deg[i]);
}
__global__ void k_scanA() {
    __shared__ int ws[32];
    int t = threadIdx.x, lane = t & 31, wid = t >> 5;
    int i = blockIdx.x * 1024 + t;
    int v = (i < N_NODES) ? (g_deg[i] - 1) : 0;
    int x = v;
    #pragma unroll
    for (int off = 1; off < 32; off <<= 1) {
        int y = __shfl_up_sync(0xffffffffu, x, off);
        if (lane >= off) x += y;
    }
    if (lane == 31) ws[wid] = x;
    __syncthreads();
    if (wid == 0) {
        int w = ws[lane];
        int xs = w;
        #pragma unroll
        for (int off = 1; off < 32; off <<= 1) {
            int y = __shfl_up_sync(0xffffffffu, xs, off);
            if (lane >= off) xs += y;
        }
        ws[lane] = xs - w;
    }
    __syncthreads();
    int excl = x - v + ws[wid];
    if (i < N_NODES) g_rowptr[i] = excl;
    if (t == 1023) g_bsum[blockIdx.x] = excl + v;
}
__global__ void k_scanB(int nblk) {
    int s = 0;
    for (int b = 0; b < nblk; b++) { int t = g_bsum[b]; g_bsum[b] = s; s += t; }
    g_rowptr[N_NODES] = s;
}
__global__ void k_scanC() {
    int i = blockIdx.x * blockDim.x + threadIdx.x;
    if (i < N_NODES) g_rowptr[i] += g_bsum[i >> 10];
}
__global__ void k_fill_csr(const int* __restrict__ row, const int* __restrict__ col) {
    int e = blockIdx.x * blockDim.x + threadIdx.x;
    if (e >= N_EDGES) return;
    int r = row[e], c = col[e];
    int pos = g_rowptr[r] + atomicAdd(&g_fill[r], 1);
    g_ecol[pos] = c;
    g_ew[pos] = 0.9f * g_dinv[r] * g_dinv[c];
}
// Wp^T split: g_wth/l[l][n][k] = split(theta*W[l][k][n] + (1-theta)*(k==n))
__global__ void k_wt(const float* __restrict__ cw) {
    int idx = blockIdx.x * blockDim.x + threadIdx.x;
    if (idx >= NLAYERS * NHID * NHID) return;
    int l = idx >> 14, n = (idx >> 7) & 127, k = idx & 127;
    float theta = logf(0.5f / (float)(l + 1) + 1.0f);
    float v = theta * cw[l * 16384 + k * 128 + n];
    if (k == n) v += 1.0f - theta;
    __nv_bfloat16 h = __float2bfloat16(v);
    g_wth[idx] = h;
    g_wtl[idx] = __float2bfloat16(v - __bfloat162float(h));
}
__global__ void k_f0t(const float* __restrict__ w) {
    int idx = blockIdx.x * blockDim.x + threadIdx.x;
    if (idx >= NHID * NFEAT) return;
    int n = idx >> 9, k = idx & 511;
    float v = w[k * NHID + n];
    __nv_bfloat16 h = __float2bfloat16(v);
    g_f0h[idx] = h;
    g_f0l[idx] = __float2bfloat16(v - __bfloat162float(h));
}
__global__ void k_f1t(const float* __restrict__ w) {
    int idx = blockIdx.x * blockDim.x + threadIdx.x;
    if (idx >= NHID * NHID) return;
    int n = idx >> 7, k = idx & 127;
    float v = w[k * NHID + n];
    __nv_bfloat16 h = __float2bfloat16(v);
    g_f1h[idx] = h;
    g_f1l[idx] = __float2bfloat16(v - __bfloat162float(h));
}
__global__ void k_xsplit(const float* __restrict__ x) {
    int i4 = blockIdx.x * blockDim.x + threadIdx.x;
    if (i4 >= (N_NODES * NFEAT) / 4) return;
    float4 v = ((const float4*)x)[i4];
    uint32_t h01 = pack_bf16(v.x, v.y), h23 = pack_bf16(v.z, v.w);
    float rx = v.x - __bfloat162float(__float2bfloat16(v.x));
    float ry = v.y - __bfloat162float(__float2bfloat16(v.y));
    float rz = v.z - __bfloat162float(__float2bfloat16(v.z));
    float rw = v.w - __bfloat162float(__float2bfloat16(v.w));
    uint32_t l01 = pack_bf16(rx, ry), l23 = pack_bf16(rz, rw);
    ((uint2*)g_xh)[i4] = make_uint2(h01, h23);
    ((uint2*)g_xl)[i4] = make_uint2(l01, l23);
}

// ---------------- SpMM: sup = 0.9*(A_norm h) + 0.1*h0, written as bf16 hi/lo ----------------
__global__ void spmm_kernel(const float* __restrict__ hin) {
    int gw = (blockIdx.x * blockDim.x + threadIdx.x) >> 5;
    if (gw >= N_NODES) return;
    int lane = threadIdx.x & 31;
    float dr = g_dinv[gw];
    float sw = 0.9f * dr * dr;
    float4 a  = ((const float4*)(hin  + (size_t)gw * NHID))[lane];
    float4 b0 = ((const float4*)(g_h0 + (size_t)gw * NHID))[lane];
    float4 acc;
    acc.x = fmaf(sw, a.x, 0.1f * b0.x);
    acc.y = fmaf(sw, a.y, 0.1f * b0.y);
    acc.z = fmaf(sw, a.z, 0.1f * b0.z);
    acc.w = fmaf(sw, a.w, 0.1f * b0.w);
    int beg = g_rowptr[gw], end = g_rowptr[gw + 1];
    #pragma unroll 4
    for (int j = beg; j < end; j++) {
        int c = g_ecol[j];
        float w = g_ew[j];
        float4 v = ((const float4*)(hin + (size_t)c * NHID))[lane];
        acc.x = fmaf(w, v.x, acc.x);
        acc.y = fmaf(w, v.y, acc.y);
        acc.z = fmaf(w, v.z, acc.z);
        acc.w = fmaf(w, v.w, acc.w);
    }
    uint32_t h01 = pack_bf16(acc.x, acc.y), h23 = pack_bf16(acc.z, acc.w);
    float rx = acc.x - __bfloat162float(__float2bfloat16(acc.x));
    float ry = acc.y - __bfloat162float(__float2bfloat16(acc.y));
    float rz = acc.z - __bfloat162float(__float2bfloat16(acc.z));
    float rw = acc.w - __bfloat162float(__float2bfloat16(acc.w));
    uint32_t l01 = pack_bf16(rx, ry), l23 = pack_bf16(rz, rw);
    ((uint2*)(g_sh + (size_t)gw * NHID))[lane] = make_uint2(h01, h23);
    ((uint2*)(g_sl + (size_t)gw * NHID))[lane] = make_uint2(l01, l23);
}

// ---------------- HMMA bf16x3 GEMM: C[M,128] = A[M,K] @ B[128,K]^T (+bias)(+relu) -----------
// A as bf16 hi/lo [M,K] row-major; B row n holds W[:,n] (pre-transposed), bf16 hi/lo.
// CTA tile 128x128, 8 warps (4x2), warp tile 32x64, BK=64, 2-stage cp.async pipeline.
// Smem row layout: 64 bf16 = 128B/row, 16B chunk c stored at (c ^ (row&7)).
__global__ __launch_bounds__(256)
void gemm_tc(const __nv_bfloat16* __restrict__ Ah, const __nv_bfloat16* __restrict__ Al,
             const __nv_bfloat16* __restrict__ Bh, const __nv_bfloat16* __restrict__ Bl,
             const float* __restrict__ bias, float* __restrict__ C,
             __nv_bfloat16* __restrict__ Coh, __nv_bfloat16* __restrict__ Col,
             int M, int K, int do_relu) {
    extern __shared__ char smem[];
    const uint32_t sb = smem_u32(smem);
    const int tid = threadIdx.x;
    const int warp = tid >> 5, lane = tid & 31;
    const int wm = warp & 3, wn = warp >> 2;
    const int row0 = blockIdx.x * BM;

    // loader: thread t covers row t>>1, chunks (t&1)*4 .. +3
    const int lr = tid >> 1;
    const int lc0 = (tid & 1) * 4;
    const bool avalid = (row0 + lr) < M;
    const size_t arow = avalid ? (size_t)(row0 + lr) : 0;

    float acc[2][8][4];
    #pragma unroll
    for (int m = 0; m < 2; m++)
        #pragma unroll
        for (int j = 0; j < 8; j++)
            #pragma unroll
            for (int q = 0; q < 4; q++) acc[m][j][q] = 0.0f;

    const int nchunk = K / BK;

    auto load_stage = [&](int s, int k0) {
        const uint32_t rbase = sb + s * STAGE_BYTES + lr * 128;
        const __nv_bfloat16* pah = Ah + arow * K + k0;
        const __nv_bfloat16* pal = Al + arow * K + k0;
        const __nv_bfloat16* pbh = Bh + (size_t)lr * K + k0;
        const __nv_bfloat16* pbl = Bl + (size_t)lr * K + k0;
        #pragma unroll
        for (int i = 0; i < 4; i++) {
            int c = lc0 + i;
            uint32_t off = (uint32_t)((c ^ (lr & 7)) << 4);
            cp16(rbase + off,                  pah + c * 8, avalid);
            cp16(rbase + TILE_BYTES + off,     pal + c * 8, avalid);
            cp16(rbase + 2 * TILE_BYTES + off, pbh + c * 8, true);
            cp16(rbase + 3 * TILE_BYTES + off, pbl + c * 8, true);
        }
    };

    load_stage(0, 0);
    cp_commit();

    for (int kc = 0; kc < nchunk; kc++) {
        if (kc + 1 < nchunk) load_stage((kc + 1) & 1, (kc + 1) * BK);
        cp_commit();
        cp_wait1();
        __syncthreads();
        const uint32_t sbase = sb + (kc & 1) * STAGE_BYTES;
        #pragma unroll
        for (int kk = 0; kk < 4; kk++) {
            uint32_t ahf[2][4], alf[2][4];
            #pragma unroll
            for (int m = 0; m < 2; m++) {
                int r = wm * 32 + m * 16 + (lane & 15);
                int cq = kk * 2 + (lane >> 4);
                uint32_t ad = sbase + r * 128 + (uint32_t)((cq ^ (r & 7)) << 4);
                ldsm4(ahf[m], ad);
                ldsm4(alf[m], ad + TILE_BYTES);
            }
            uint32_t bhf[8][2], blf[8][2];
            #pragma unroll
            for (int jp = 0; jp < 4; jp++) {
                int g = lane >> 3;
                int nr = wn * 64 + jp * 16 + ((g >> 1) << 3) + (lane & 7);
                int cq = kk * 2 + (g & 1);
                uint32_t bd = sbase + 2 * TILE_BYTES + nr * 128 +
                              (uint32_t)((cq ^ (nr & 7)) << 4);
                uint32_t t[4];
                ldsm4(t, bd);
                bhf[jp * 2][0] = t[0]; bhf[jp * 2][1] = t[1];
                bhf[jp * 2 + 1][0] = t[2]; bhf[jp * 2 + 1][1] = t[3];
                ldsm4(t, bd + TILE_BYTES);
                blf[jp * 2][0] = t[0]; blf[jp * 2][1] = t[1];
                blf[jp * 2 + 1][0] = t[2]; blf[jp * 2 + 1][1] = t[3];
            }
            #pragma unroll
            for (int m = 0; m < 2; m++)
                #pragma unroll
                for (int j = 0; j < 8; j++) {
                    mma16816(acc[m][j], ahf[m], bhf[j]);
                    mma16816(acc[m][j], ahf[m], blf[j]);
                    mma16816(acc[m][j], alf[m], bhf[j]);
                }
        }
        __syncthreads();
    }

    // epilogue
    #pragma unroll
    for (int m = 0; m < 2; m++) {
        int r = row0 + wm * 32 + m * 16 + (lane >> 2);
        #pragma unroll
        for (int j = 0; j < 8; j++) {
            int cc = wn * 64 + j * 8 + (lane & 3) * 2;
            float b0v = bias ? bias[cc] : 0.0f;
            float b1v = bias ? bias[cc + 1] : 0.0f;
            float v0 = acc[m][j][0] + b0v, v1 = acc[m][j][1] + b1v;
            float v2 = acc[m][j][2] + b0v, v3 = acc[m][j][3] + b1v;
            if (do_relu) {
                v0 = fmaxf(v0, 0.f); v1 = fmaxf(v1, 0.f);
                v2 = fmaxf(v2, 0.f); v3 = fmaxf(v3, 0.f);
            }
            if (r < M) {
                *(float2*)(C + (size_t)r * 128 + cc) = make_float2(v0, v1);
                if (Coh) {
                    *(uint32_t*)(Coh + (size_t)r * 128 + cc) = pack_bf16(v0, v1);
                    float r0 = v0 - __bfloat162float(__float2bfloat16(v0));
                    float r1 = v1 - __bfloat162float(__float2bfloat16(v1));
                    *(uint32_t*)(Col + (size_t)r * 128 + cc) = pack_bf16(r0, r1);
                }
            }
            if (r + 8 < M) {
                *(float2*)(C + (size_t)(r + 8) * 128 + cc) = make_float2(v2, v3);
                if (Coh) {
                    *(uint32_t*)(Coh + (size_t)(r + 8) * 128 + cc) = pack_bf16(v2, v3);
                    float r2 = v2 - __bfloat162float(__float2bfloat16(v2));
                    float r3 = v3 - __bfloat162float(__float2bfloat16(v3));
                    *(uint32_t*)(Col + (size_t)(r + 8) * 128 + cc) = pack_bf16(r2, r3);
                }
            }
        }
    }
}

// ---------------- launch ----------------
extern "C" void kernel_launch(void* const* d_in, const int* in_sizes, int n_in,
                              void* d_out, int out_size) {
    const float* x      = (const float*)d_in[0];
    const int*   eidx   = (const int*)d_in[1];
    const float* conv_w = (const float*)d_in[2];
    const float* fc0_w  = (const float*)d_in[3];
    const float* fc0_b  = (const float*)d_in[4];
    const float* fc1_w  = (const float*)d_in[5];
    const float* fc1_b  = (const float*)d_in[6];
    float* out = (float*)d_out;
    const int* row = eidx;
    const int* col = eidx + N_EDGES;

    float *h0, *bufA, *bufB;
    __nv_bfloat16 *sh, *sl, *xh, *xl, *wth, *wtl, *f0h, *f0l, *f1h, *f1l;
    cudaGetSymbolAddress((void**)&h0,   g_h0);
    cudaGetSymbolAddress((void**)&bufA, g_bufA);
    cudaGetSymbolAddress((void**)&bufB, g_bufB);
    cudaGetSymbolAddress((void**)&sh,   g_sh);
    cudaGetSymbolAddress((void**)&sl,   g_sl);
    cudaGetSymbolAddress((void**)&xh,   g_xh);
    cudaGetSymbolAddress((void**)&xl,   g_xl);
    cudaGetSymbolAddress((void**)&wth,  g_wth);
    cudaGetSymbolAddress((void**)&wtl,  g_wtl);
    cudaGetSymbolAddress((void**)&f0h,  g_f0h);
    cudaGetSymbolAddress((void**)&f0l,  g_f0l);
    cudaGetSymbolAddress((void**)&f1h,  g_f1h);
    cudaGetSymbolAddress((void**)&f1l,  g_f1l);

    const int SMEM_BYTES = 2 * STAGE_BYTES;  // 128 KB
    static int smem_set = 0;
    if (!smem_set) {
        cudaFuncSetAttribute(gemm_tc, cudaFuncAttributeMaxDynamicSharedMemorySize, SMEM_BYTES);
        smem_set = 1;
    }

    const int NB_N = (N_NODES + 255) / 256;
    const int NB_E = (N_EDGES + 255) / 256;
    const int NB_G = (N_NODES + BM - 1) / BM;   // 391
    const int NB_S = (N_NODES + 1023) / 1024;   // 49

    k_init_nodes<<<NB_N, 256>>>();
    k_count<<<NB_E, 256>>>(row);
    k_dinv<<<NB_N, 256>>>();
    k_scanA<<<NB_S, 1024>>>();
    k_scanB<<<1, 1>>>(NB_S);
    k_scanC<<<NB_N, 256>>>();
    k_fill_csr<<<NB_E, 256>>>(row, col);
    k_wt<<<(NLAYERS * NHID * NHID) / 256, 256>>>(conv_w);
    k_f0t<<<(NHID * NFEAT) / 256, 256>>>(fc0_w);
    k_f1t<<<(NHID * NHID) / 256, 256>>>(fc1_w);
    k_xsplit<<<(N_NODES * NFEAT / 4 + 255) / 256, 256>>>(x);

    // h0 = relu(x @ fc0_w + fc0_b)
    gemm_tc<<<NB_G, 256, SMEM_BYTES>>>(xh, xl, f0h, f0l, fc0_b, h0,
                                       nullptr, nullptr, N_NODES, NFEAT, 1);

    const float* hin = h0;
    for (int l = 0; l < NLAYERS; l++) {
        float* hout = (l & 1) ? bufB : bufA;
        spmm_kernel<<<(N_NODES * 32 + 255) / 256, 256>>>(hin);
        bool last = (l == NLAYERS - 1);
        gemm_tc<<<NB_G, 256, SMEM_BYTES>>>(sh, sl,
                                           wth + (size_t)l * NHID * NHID,
                                           wtl + (size_t)l * NHID * NHID,
                                           nullptr, hout,
                                           last ? sh : nullptr, last ? sl : nullptr,
                                           N_NODES, NHID, 1);
        hin = hout;
    }

    // out = h @ fc1_w + fc1_b
    gemm_tc<<<NB_G, 256, SMEM_BYTES>>>(sh, sl, f1h, f1l, fc1_b, out,
                                       nullptr, nullptr, N_NODES, NHID, 0);
}

// round 4
// speedup vs baseline: 1.4189x; 1.0684x over previous
#include <cuda_runtime.h>
#include <cuda_bf16.h>
#include <cuda_fp16.h>
#include <math.h>
#include <stdint.h>

#define N_NODES 50000
#define N_EDGES 800000
#define NFEAT   512
#define NHID    128
#define NLAYERS 16

#define BM 128
#define BN 128
#define BK 64
#define STAGE_BYTES 65536
#define TILE_BYTES  16384

// ---------------- scratch (device globals) ----------------
__device__ __align__(16)  int   g_deg[N_NODES];
__device__ __align__(16)  float g_dinv[N_NODES];
__device__ __align__(16)  int   g_rowptr[N_NODES + 1];
__device__ __align__(16)  int   g_fill[N_NODES];
__device__ __align__(16)  int   g_ecol[N_EDGES];
__device__ __align__(16)  float g_ew[N_EDGES];
__device__ __align__(16)  int   g_bsum[64];

__device__ __align__(128) float  g_h0[(size_t)N_NODES * NHID];
__device__ __align__(128) __half g_h16A[(size_t)N_NODES * NHID];
__device__ __align__(128) __half g_h16B[(size_t)N_NODES * NHID];
__device__ __align__(128) __nv_bfloat16 g_sh[(size_t)N_NODES * NHID];
__device__ __align__(128) __nv_bfloat16 g_sl[(size_t)N_NODES * NHID];
__device__ __align__(128) __nv_bfloat16 g_xh[(size_t)N_NODES * NFEAT];
__device__ __align__(128) __nv_bfloat16 g_xl[(size_t)N_NODES * NFEAT];
__device__ __align__(128) __nv_bfloat16 g_wth[NLAYERS * NHID * NHID];
__device__ __align__(128) __nv_bfloat16 g_wtl[NLAYERS * NHID * NHID];
__device__ __align__(128) __nv_bfloat16 g_f0h[NHID * NFEAT];
__device__ __align__(128) __nv_bfloat16 g_f0l[NHID * NFEAT];
__device__ __align__(128) __nv_bfloat16 g_f1h[NHID * NHID];
__device__ __align__(128) __nv_bfloat16 g_f1l[NHID * NHID];

// ---------------- PTX helpers (baseline sm_80+ only) ----------------
__device__ __forceinline__ uint32_t smem_u32(const void* p) {
    uint32_t a;
    asm("{ .reg .u64 t; cvta.to.shared.u64 t, %1; cvt.u32.u64 %0, t; }" : "=r"(a) : "l"(p));
    return a;
}
__device__ __forceinline__ void cp16(uint32_t dst, const void* src, bool valid) {
    asm volatile("cp.async.cg.shared.global [%0], [%1], 16, %2;"
                 :: "r"(dst), "l"(src), "r"(valid ? 16 : 0) : "memory");
}
__device__ __forceinline__ void cp_commit() {
    asm volatile("cp.async.commit_group;" ::: "memory");
}
__device__ __forceinline__ void cp_wait1() {
    asm volatile("cp.async.wait_group 1;" ::: "memory");
}
__device__ __forceinline__ void ldsm4(uint32_t* r, uint32_t addr) {
    asm volatile("ldmatrix.sync.aligned.m8n8.x4.shared.b16 {%0,%1,%2,%3}, [%4];"
                 : "=r"(r[0]), "=r"(r[1]), "=r"(r[2]), "=r"(r[3]) : "r"(addr));
}
__device__ __forceinline__ void mma16816(float* d, const uint32_t* a, const uint32_t* b) {
    asm volatile("mma.sync.aligned.m16n8k16.row.col.f32.bf16.bf16.f32 "
                 "{%0,%1,%2,%3}, {%4,%5,%6,%7}, {%8,%9}, {%0,%1,%2,%3};"
                 : "+f"(d[0]), "+f"(d[1]), "+f"(d[2]), "+f"(d[3])
                 : "r"(a[0]), "r"(a[1]), "r"(a[2]), "r"(a[3]), "r"(b[0]), "r"(b[1]));
}
__device__ __forceinline__ uint32_t pack_bf16(float a, float b) {
    __nv_bfloat16 ha = __float2bfloat16(a), hb = __float2bfloat16(b);
    return ((uint32_t)*(unsigned short*)&hb << 16) | *(unsigned short*)&ha;
}
__device__ __forceinline__ uint32_t pack_f16(float a, float b) {
    __half ha = __float2half_rn(a), hb = __float2half_rn(b);
    return ((uint32_t)*(unsigned short*)&hb << 16) | *(unsigned short*)&ha;
}

// ---------------- preprocessing kernels ----------------
__global__ void k_init_nodes() {
    int i = blockIdx.x * blockDim.x + threadIdx.x;
    if (i < N_NODES) { g_deg[i] = 1; g_fill[i] = 0; }
}
__global__ void k_count(const int* __restrict__ row) {
    int e = blockIdx.x * blockDim.x + threadIdx.x;
    if (e < N_EDGES) atomicAdd(&g_deg[row[e]], 1);
}
__global__ void k_dinv() {
    int i = blockIdx.x * blockDim.x + threadIdx.x;
    if (i < N_NODES) g_dinv[i] = rsqrtf((float)g_deg[i]);
}
__global__ void k_scanA() {
    __shared__ int ws[32];
    int t = threadIdx.x, lane = t & 31, wid = t >> 5;
    int i = blockIdx.x * 1024 + t;
    int v = (i < N_NODES) ? (g_deg[i] - 1) : 0;
    int x = v;
    #pragma unroll
    for (int off = 1; off < 32; off <<= 1) {
        int y = __shfl_up_sync(0xffffffffu, x, off);
        if (lane >= off) x += y;
    }
    if (lane == 31) ws[wid] = x;
    __syncthreads();
    if (wid == 0) {
        int w = ws[lane];
        int xs = w;
        #pragma unroll
        for (int off = 1; off < 32; off <<= 1) {
            int y = __shfl_up_sync(0xffffffffu, xs, off);
            if (lane >= off) xs += y;
        }
        ws[lane] = xs - w;
    }
    __syncthreads();
    int excl = x - v + ws[wid];
    if (i < N_NODES) g_rowptr[i] = excl;
    if (t == 1023) g_bsum[blockIdx.x] = excl + v;
}
__global__ void k_scanB(int nblk) {
    int s = 0;
    for (int b = 0; b < nblk; b++) { int t = g_bsum[b]; g_bsum[b] = s; s += t; }
    g_rowptr[N_NODES] = s;
}
__global__ void k_scanC() {
    int i = blockIdx.x * blockDim.x + threadIdx.x;
    if (i < N_NODES) g_rowptr[i] += g_bsum[i >> 10];
}
__global__ void k_fill_csr(const int* __restrict__ row, const int* __restrict__ col) {
    int e = blockIdx.x * blockDim.x + threadIdx.x;
    if (e >= N_EDGES) return;
    int r = row[e], c = col[e];
    int pos = g_rowptr[r] + atomicAdd(&g_fill[r], 1);
    g_ecol[pos] = c;
    g_ew[pos] = 0.9f * g_dinv[r] * g_dinv[c];
}
__global__ void k_wt(const float* __restrict__ cw) {
    int idx = blockIdx.x * blockDim.x + threadIdx.x;
    if (idx >= NLAYERS * NHID * NHID) return;
    int l = idx >> 14, n = (idx >> 7) & 127, k = idx & 127;
    float theta = logf(0.5f / (float)(l + 1) + 1.0f);
    float v = theta * cw[l * 16384 + k * 128 + n];
    if (k == n) v += 1.0f - theta;
    __nv_bfloat16 h = __float2bfloat16(v);
    g_wth[idx] = h;
    g_wtl[idx] = __float2bfloat16(v - __bfloat162float(h));
}
__global__ void k_f0t(const float* __restrict__ w) {
    int idx = blockIdx.x * blockDim.x + threadIdx.x;
    if (idx >= NHID * NFEAT) return;
    int n = idx >> 9, k = idx & 511;
    float v = w[k * NHID + n];
    __nv_bfloat16 h = __float2bfloat16(v);
    g_f0h[idx] = h;
    g_f0l[idx] = __float2bfloat16(v - __bfloat162float(h));
}
__global__ void k_f1t(const float* __restrict__ w) {
    int idx = blockIdx.x * blockDim.x + threadIdx.x;
    if (idx >= NHID * NHID) return;
    int n = idx >> 7, k = idx & 127;
    float v = w[k * NHID + n];
    __nv_bfloat16 h = __float2bfloat16(v);
    g_f1h[idx] = h;
    g_f1l[idx] = __float2bfloat16(v - __bfloat162float(h));
}
__global__ void k_xsplit(const float* __restrict__ x) {
    int i4 = blockIdx.x * blockDim.x + threadIdx.x;
    if (i4 >= (N_NODES * NFEAT) / 4) return;
    float4 v = ((const float4*)x)[i4];
    uint32_t h01 = pack_bf16(v.x, v.y), h23 = pack_bf16(v.z, v.w);
    float rx = v.x - __bfloat162float(__float2bfloat16(v.x));
    float ry = v.y - __bfloat162float(__float2bfloat16(v.y));
    float rz = v.z - __bfloat162float(__float2bfloat16(v.z));
    float rw = v.w - __bfloat162float(__float2bfloat16(v.w));
    uint32_t l01 = pack_bf16(rx, ry), l23 = pack_bf16(rz, rw);
    ((uint2*)g_xh)[i4] = make_uint2(h01, h23);
    ((uint2*)g_xl)[i4] = make_uint2(l01, l23);
}

// ---------------- SpMM: sup = 0.9*(A_norm h) + 0.1*h0; h gathered in fp16 ----------------
// one warp per row; lane owns 4 features (uint2 = 4 halves).
__global__ void spmm_kernel(const __half* __restrict__ hin) {
    int gw = (blockIdx.x * blockDim.x + threadIdx.x) >> 5;
    if (gw >= N_NODES) return;
    int lane = threadIdx.x & 31;
    float dr = g_dinv[gw];
    float sw = 0.9f * dr * dr;

    uint2 selfp = ((const uint2*)(hin + (size_t)gw * NHID))[lane];
    float2 s01 = __half22float2(*(const __half2*)&selfp.x);
    float2 s23 = __half22float2(*(const __half2*)&selfp.y);
    float4 b0 = ((const float4*)(g_h0 + (size_t)gw * NHID))[lane];

    float4 acc;
    acc.x = fmaf(sw, s01.x, 0.1f * b0.x);
    acc.y = fmaf(sw, s01.y, 0.1f * b0.y);
    acc.z = fmaf(sw, s23.x, 0.1f * b0.z);
    acc.w = fmaf(sw, s23.y, 0.1f * b0.w);

    int beg = g_rowptr[gw], end = g_rowptr[gw + 1];
    #pragma unroll 4
    for (int j = beg; j < end; j++) {
        int c = g_ecol[j];
        float w = g_ew[j];
        uint2 vp = ((const uint2*)(hin + (size_t)c * NHID))[lane];
        float2 v01 = __half22float2(*(const __half2*)&vp.x);
        float2 v23 = __half22float2(*(const __half2*)&vp.y);
        acc.x = fmaf(w, v01.x, acc.x);
        acc.y = fmaf(w, v01.y, acc.y);
        acc.z = fmaf(w, v23.x, acc.z);
        acc.w = fmaf(w, v23.y, acc.w);
    }

    uint32_t h01 = pack_bf16(acc.x, acc.y), h23 = pack_bf16(acc.z, acc.w);
    float rx = acc.x - __bfloat162float(__float2bfloat16(acc.x));
    float ry = acc.y - __bfloat162float(__float2bfloat16(acc.y));
    float rz = acc.z - __bfloat162float(__float2bfloat16(acc.z));
    float rw = acc.w - __bfloat162float(__float2bfloat16(acc.w));
    uint32_t l01 = pack_bf16(rx, ry), l23 = pack_bf16(rz, rw);
    ((uint2*)(g_sh + (size_t)gw * NHID))[lane] = make_uint2(h01, h23);
    ((uint2*)(g_sl + (size_t)gw * NHID))[lane] = make_uint2(l01, l23);
}

// ---------------- HMMA bf16x3 GEMM: C = A @ B^T (+bias)(+relu), flexible outputs ----------
__global__ __launch_bounds__(256)
void gemm_tc(const __nv_bfloat16* __restrict__ Ah, const __nv_bfloat16* __restrict__ Al,
             const __nv_bfloat16* __restrict__ Bh, const __nv_bfloat16* __restrict__ Bl,
             const float* __restrict__ bias,
             float* __restrict__ Cf, __half* __restrict__ C16,
             __nv_bfloat16* __restrict__ Coh, __nv_bfloat16* __restrict__ Col,
             int M, int K, int do_relu) {
    extern __shared__ char smem[];
    const uint32_t sb = smem_u32(smem);
    const int tid = threadIdx.x;
    const int warp = tid >> 5, lane = tid & 31;
    const int wm = warp & 3, wn = warp >> 2;
    const int row0 = blockIdx.x * BM;

    const int lr = tid >> 1;
    const int lc0 = (tid & 1) * 4;
    const bool avalid = (row0 + lr) < M;
    const size_t arow = avalid ? (size_t)(row0 + lr) : 0;

    float acc[2][8][4];
    #pragma unroll
    for (int m = 0; m < 2; m++)
        #pragma unroll
        for (int j = 0; j < 8; j++)
            #pragma unroll
            for (int q = 0; q < 4; q++) acc[m][j][q] = 0.0f;

    const int nchunk = K / BK;

    auto load_stage = [&](int s, int k0) {
        const uint32_t rbase = sb + s * STAGE_BYTES + lr * 128;
        const __nv_bfloat16* pah = Ah + arow * K + k0;
        const __nv_bfloat16* pal = Al + arow * K + k0;
        const __nv_bfloat16* pbh = Bh + (size_t)lr * K + k0;
        const __nv_bfloat16* pbl = Bl + (size_t)lr * K + k0;
        #pragma unroll
        for (int i = 0; i < 4; i++) {
            int c = lc0 + i;
            uint32_t off = (uint32_t)((c ^ (lr & 7)) << 4);
            cp16(rbase + off,                  pah + c * 8, avalid);
            cp16(rbase + TILE_BYTES + off,     pal + c * 8, avalid);
            cp16(rbase + 2 * TILE_BYTES + off, pbh + c * 8, true);
            cp16(rbase + 3 * TILE_BYTES + off, pbl + c * 8, true);
        }
    };

    load_stage(0, 0);
    cp_commit();

    for (int kc = 0; kc < nchunk; kc++) {
        if (kc + 1 < nchunk) load_stage((kc + 1) & 1, (kc + 1) * BK);
        cp_commit();
        cp_wait1();
        __syncthreads();
        const uint32_t sbase = sb + (kc & 1) * STAGE_BYTES;
        #pragma unroll
        for (int kk = 0; kk < 4; kk++) {
            uint32_t ahf[2][4], alf[2][4];
            #pragma unroll
            for (int m = 0; m < 2; m++) {
                int r = wm * 32 + m * 16 + (lane & 15);
                int cq = kk * 2 + (lane >> 4);
                uint32_t ad = sbase + r * 128 + (uint32_t)((cq ^ (r & 7)) << 4);
                ldsm4(ahf[m], ad);
                ldsm4(alf[m], ad + TILE_BYTES);
            }
            uint32_t bhf[8][2], blf[8][2];
            #pragma unroll
            for (int jp = 0; jp < 4; jp++) {
                int g = lane >> 3;
                int nr = wn * 64 + jp * 16 + ((g >> 1) << 3) + (lane & 7);
                int cq = kk * 2 + (g & 1);
                uint32_t bd = sbase + 2 * TILE_BYTES + nr * 128 +
                              (uint32_t)((cq ^ (nr & 7)) << 4);
                uint32_t t[4];
                ldsm4(t, bd);
                bhf[jp * 2][0] = t[0]; bhf[jp * 2][1] = t[1];
                bhf[jp * 2 + 1][0] = t[2]; bhf[jp * 2 + 1][1] = t[3];
                ldsm4(t, bd + TILE_BYTES);
                blf[jp * 2][0] = t[0]; blf[jp * 2][1] = t[1];
                blf[jp * 2 + 1][0] = t[2]; blf[jp * 2 + 1][1] = t[3];
            }
            #pragma unroll
            for (int m = 0; m < 2; m++)
                #pragma unroll
                for (int j = 0; j < 8; j++) {
                    mma16816(acc[m][j], ahf[m], bhf[j]);
                    mma16816(acc[m][j], ahf[m], blf[j]);
                    mma16816(acc[m][j], alf[m], bhf[j]);
                }
        }
        __syncthreads();
    }

    // epilogue
    #pragma unroll
    for (int m = 0; m < 2; m++) {
        int rbase_ = row0 + wm * 32 + m * 16 + (lane >> 2);
        #pragma unroll
        for (int j = 0; j < 8; j++) {
            int cc = wn * 64 + j * 8 + (lane & 3) * 2;
            float b0v = bias ? bias[cc] : 0.0f;
            float b1v = bias ? bias[cc + 1] : 0.0f;
            float v0 = acc[m][j][0] + b0v, v1 = acc[m][j][1] + b1v;
            float v2 = acc[m][j][2] + b0v, v3 = acc[m][j][3] + b1v;
            if (do_relu) {
                v0 = fmaxf(v0, 0.f); v1 = fmaxf(v1, 0.f);
                v2 = fmaxf(v2, 0.f); v3 = fmaxf(v3, 0.f);
            }
            #pragma unroll
            for (int half_ = 0; half_ < 2; half_++) {
                int r = rbase_ + half_ * 8;
                float va = half_ ? v2 : v0, vb = half_ ? v3 : v1;
                if (r < M) {
                    if (Cf)  *(float2*)(Cf + (size_t)r * 128 + cc) = make_float2(va, vb);
                    if (C16) *(uint32_t*)(C16 + (size_t)r * 128 + cc) = pack_f16(va, vb);
                    if (Coh) {
                        *(uint32_t*)(Coh + (size_t)r * 128 + cc) = pack_bf16(va, vb);
                        float ra = va - __bfloat162float(__float2bfloat16(va));
                        float rb = vb - __bfloat162float(__float2bfloat16(vb));
                        *(uint32_t*)(Col + (size_t)r * 128 + cc) = pack_bf16(ra, rb);
                    }
                }
            }
        }
    }
}

// ---------------- launch ----------------
extern "C" void kernel_launch(void* const* d_in, const int* in_sizes, int n_in,
                              void* d_out, int out_size) {
    const float* x      = (const float*)d_in[0];
    const int*   eidx   = (const int*)d_in[1];
    const float* conv_w = (const float*)d_in[2];
    const float* fc0_w  = (const float*)d_in[3];
    const float* fc0_b  = (const float*)d_in[4];
    const float* fc1_w  = (const float*)d_in[5];
    const float* fc1_b  = (const float*)d_in[6];
    float* out = (float*)d_out;
    const int* row = eidx;
    const int* col = eidx + N_EDGES;

    float *h0;
    __half *h16A, *h16B;
    __nv_bfloat16 *sh, *sl, *xh, *xl, *wth, *wtl, *f0h, *f0l, *f1h, *f1l;
    cudaGetSymbolAddress((void**)&h0,   g_h0);
    cudaGetSymbolAddress((void**)&h16A, g_h16A);
    cudaGetSymbolAddress((void**)&h16B, g_h16B);
    cudaGetSymbolAddress((void**)&sh,   g_sh);
    cudaGetSymbolAddress((void**)&sl,   g_sl);
    cudaGetSymbolAddress((void**)&xh,   g_xh);
    cudaGetSymbolAddress((void**)&xl,   g_xl);
    cudaGetSymbolAddress((void**)&wth,  g_wth);
    cudaGetSymbolAddress((void**)&wtl,  g_wtl);
    cudaGetSymbolAddress((void**)&f0h,  g_f0h);
    cudaGetSymbolAddress((void**)&f0l,  g_f0l);
    cudaGetSymbolAddress((void**)&f1h,  g_f1h);
    cudaGetSymbolAddress((void**)&f1l,  g_f1l);

    const int SMEM_BYTES = 2 * STAGE_BYTES;  // 128 KB
    static int smem_set = 0;
    if (!smem_set) {
        cudaFuncSetAttribute(gemm_tc, cudaFuncAttributeMaxDynamicSharedMemorySize, SMEM_BYTES);
        smem_set = 1;
    }

    const int NB_N = (N_NODES + 255) / 256;
    const int NB_E = (N_EDGES + 255) / 256;
    const int NB_G = (N_NODES + BM - 1) / BM;   // 391
    const int NB_S = (N_NODES + 1023) / 1024;   // 49

    k_init_nodes<<<NB_N, 256>>>();
    k_count<<<NB_E, 256>>>(row);
    k_dinv<<<NB_N, 256>>>();
    k_scanA<<<NB_S, 1024>>>();
    k_scanB<<<1, 1>>>(NB_S);
    k_scanC<<<NB_N, 256>>>();
    k_fill_csr<<<NB_E, 256>>>(row, col);
    k_wt<<<(NLAYERS * NHID * NHID) / 256, 256>>>(conv_w);
    k_f0t<<<(NHID * NFEAT) / 256, 256>>>(fc0_w);
    k_f1t<<<(NHID * NHID) / 256, 256>>>(fc1_w);
    k_xsplit<<<(N_NODES * NFEAT / 4 + 255) / 256, 256>>>(x);

    // h0 (fp32, for alpha-mix) + h16 (fp16, for SpMM) = relu(x @ fc0_w + fc0_b)
    gemm_tc<<<NB_G, 256, SMEM_BYTES>>>(xh, xl, f0h, f0l, fc0_b,
                                       h0, h16A, nullptr, nullptr, N_NODES, NFEAT, 1);

    const __half* hin = h16A;
    for (int l = 0; l < NLAYERS; l++) {
        spmm_kernel<<<(N_NODES * 32 + 255) / 256, 256>>>(hin);
        bool last = (l == NLAYERS - 1);
        __half* hout = (l & 1) ? h16A : h16B;
        gemm_tc<<<NB_G, 256, SMEM_BYTES>>>(sh, sl,
                                           wth + (size_t)l * NHID * NHID,
                                           wtl + (size_t)l * NHID * NHID,
                                           nullptr,
                                           nullptr,
                                           last ? nullptr : hout,
                                           last ? sh : nullptr, last ? sl : nullptr,
                                           N_NODES, NHID, 1);
        hin = hout;
    }

    // out = h @ fc1_w + fc1_b
    gemm_tc<<<NB_G, 256, SMEM_BYTES>>>(sh, sl, f1h, f1l, fc1_b,
                                       out, nullptr, nullptr, nullptr, N_NODES, NHID, 0);
}

// round 5
// speedup vs baseline: 1.8008x; 1.2692x over previous
#include <cuda_runtime.h>
#include <cuda_bf16.h>
#include <cuda_fp16.h>
#include <math.h>
#include <stdint.h>

#define N_NODES 50000
#define N_EDGES 800000
#define NFEAT   512
#define NHID    128
#define NLAYERS 16

#define BM 128
#define BN 128
#define BK 64
// per stage: A(16KB) + Bh(16KB) + Bl(16KB)
#define TILE_BYTES  16384
#define STAGE_BYTES 49152

// ---------------- scratch (device globals) ----------------
__device__ __align__(16)  int   g_deg[N_NODES];
__device__ __align__(16)  float g_dinv[N_NODES];
__device__ __align__(16)  int   g_rowptr[N_NODES + 1];
__device__ __align__(16)  int   g_fill[N_NODES];
__device__ __align__(16)  int   g_ecol[N_EDGES];
__device__ __align__(16)  float g_ew[N_EDGES];
__device__ __align__(16)  int   g_bsum[64];

__device__ __align__(128) float  g_h0[(size_t)N_NODES * NHID];
__device__ __align__(128) __half g_h16A[(size_t)N_NODES * NHID];
__device__ __align__(128) __half g_h16B[(size_t)N_NODES * NHID];
__device__ __align__(128) __half g_s16[(size_t)N_NODES * NHID];
__device__ __align__(128) __half g_x16[(size_t)N_NODES * NFEAT];
__device__ __align__(128) __half g_wth[NLAYERS * NHID * NHID];
__device__ __align__(128) __half g_wtl[NLAYERS * NHID * NHID];
__device__ __align__(128) __half g_f0h[NHID * NFEAT];
__device__ __align__(128) __half g_f0l[NHID * NFEAT];
__device__ __align__(128) __half g_f1h[NHID * NHID];
__device__ __align__(128) __half g_f1l[NHID * NHID];

// ---------------- PTX helpers (baseline sm_80+ only) ----------------
__device__ __forceinline__ uint32_t smem_u32(const void* p) {
    uint32_t a;
    asm("{ .reg .u64 t; cvta.to.shared.u64 t, %1; cvt.u32.u64 %0, t; }" : "=r"(a) : "l"(p));
    return a;
}
__device__ __forceinline__ void cp16(uint32_t dst, const void* src, bool valid) {
    asm volatile("cp.async.cg.shared.global [%0], [%1], 16, %2;"
                 :: "r"(dst), "l"(src), "r"(valid ? 16 : 0) : "memory");
}
__device__ __forceinline__ void cp_commit() {
    asm volatile("cp.async.commit_group;" ::: "memory");
}
__device__ __forceinline__ void cp_wait1() {
    asm volatile("cp.async.wait_group 1;" ::: "memory");
}
__device__ __forceinline__ void ldsm4(uint32_t* r, uint32_t addr) {
    asm volatile("ldmatrix.sync.aligned.m8n8.x4.shared.b16 {%0,%1,%2,%3}, [%4];"
                 : "=r"(r[0]), "=r"(r[1]), "=r"(r[2]), "=r"(r[3]) : "r"(addr));
}
__device__ __forceinline__ void mma16816h(float* d, const uint32_t* a, const uint32_t* b) {
    asm volatile("mma.sync.aligned.m16n8k16.row.col.f32.f16.f16.f32 "
                 "{%0,%1,%2,%3}, {%4,%5,%6,%7}, {%8,%9}, {%0,%1,%2,%3};"
                 : "+f"(d[0]), "+f"(d[1]), "+f"(d[2]), "+f"(d[3])
                 : "r"(a[0]), "r"(a[1]), "r"(a[2]), "r"(a[3]), "r"(b[0]), "r"(b[1]));
}
__device__ __forceinline__ uint32_t pack_f16(float a, float b) {
    __half ha = __float2half_rn(a), hb = __float2half_rn(b);
    return ((uint32_t)*(unsigned short*)&hb << 16) | *(unsigned short*)&ha;
}

// ---------------- preprocessing kernels ----------------
__global__ void k_init_nodes() {
    int i = blockIdx.x * blockDim.x + threadIdx.x;
    if (i < N_NODES) { g_deg[i] = 1; g_fill[i] = 0; }
}
__global__ void k_count(const int* __restrict__ row) {
    int e = blockIdx.x * blockDim.x + threadIdx.x;
    if (e < N_EDGES) atomicAdd(&g_deg[row[e]], 1);
}
__global__ void k_dinv() {
    int i = blockIdx.x * blockDim.x + threadIdx.x;
    if (i < N_NODES) g_dinv[i] = rsqrtf((float)g_deg[i]);
}
__global__ void k_scanA() {
    __shared__ int ws[32];
    int t = threadIdx.x, lane = t & 31, wid = t >> 5;
    int i = blockIdx.x * 1024 + t;
    int v = (i < N_NODES) ? (g_deg[i] - 1) : 0;
    int x = v;
    #pragma unroll
    for (int off = 1; off < 32; off <<= 1) {
        int y = __shfl_up_sync(0xffffffffu, x, off);
        if (lane >= off) x += y;
    }
    if (lane == 31) ws[wid] = x;
    __syncthreads();
    if (wid == 0) {
        int w = ws[lane];
        int xs = w;
        #pragma unroll
        for (int off = 1; off < 32; off <<= 1) {
            int y = __shfl_up_sync(0xffffffffu, xs, off);
            if (lane >= off) xs += y;
        }
        ws[lane] = xs - w;
    }
    __syncthreads();
    int excl = x - v + ws[wid];
    if (i < N_NODES) g_rowptr[i] = excl;
    if (t == 1023) g_bsum[blockIdx.x] = excl + v;
}
__global__ void k_scanB(int nblk) {
    int s = 0;
    for (int b = 0; b < nblk; b++) { int t = g_bsum[b]; g_bsum[b] = s; s += t; }
    g_rowptr[N_NODES] = s;
}
__global__ void k_scanC() {
    int i = blockIdx.x * blockDim.x + threadIdx.x;
    if (i < N_NODES) g_rowptr[i] += g_bsum[i >> 10];
}
__global__ void k_fill_csr(const int* __restrict__ row, const int* __restrict__ col) {
    int e = blockIdx.x * blockDim.x + threadIdx.x;
    if (e >= N_EDGES) return;
    int r = row[e], c = col[e];
    int pos = g_rowptr[r] + atomicAdd(&g_fill[r], 1);
    g_ecol[pos] = c;
    g_ew[pos] = 0.9f * g_dinv[r] * g_dinv[c];
}
// Wp^T fp16 split: v = theta*W[l][k][n] + (1-theta)*(k==n); h=fp16(v), l=fp16(v-h)
__global__ void k_wt(const float* __restrict__ cw) {
    int idx = blockIdx.x * blockDim.x + threadIdx.x;
    if (idx >= NLAYERS * NHID * NHID) return;
    int l = idx >> 14, n = (idx >> 7) & 127, k = idx & 127;
    float theta = logf(0.5f / (float)(l + 1) + 1.0f);
    float v = theta * cw[l * 16384 + k * 128 + n];
    if (k == n) v += 1.0f - theta;
    __half h = __float2half_rn(v);
    g_wth[idx] = h;
    g_wtl[idx] = __float2half_rn(v - __half2float(h));
}
__global__ void k_f0t(const float* __restrict__ w) {
    int idx = blockIdx.x * blockDim.x + threadIdx.x;
    if (idx >= NHID * NFEAT) return;
    int n = idx >> 9, k = idx & 511;
    float v = w[k * NHID + n];
    __half h = __float2half_rn(v);
    g_f0h[idx] = h;
    g_f0l[idx] = __float2half_rn(v - __half2float(h));
}
__global__ void k_f1t(const float* __restrict__ w) {
    int idx = blockIdx.x * blockDim.x + threadIdx.x;
    if (idx >= NHID * NHID) return;
    int n = idx >> 7, k = idx & 127;
    float v = w[k * NHID + n];
    __half h = __float2half_rn(v);
    g_f1h[idx] = h;
    g_f1l[idx] = __float2half_rn(v - __half2float(h));
}
__global__ void k_x16(const float* __restrict__ x) {
    int i4 = blockIdx.x * blockDim.x + threadIdx.x;
    if (i4 >= (N_NODES * NFEAT) / 4) return;
    float4 v = ((const float4*)x)[i4];
    ((uint2*)g_x16)[i4] = make_uint2(pack_f16(v.x, v.y), pack_f16(v.z, v.w));
}

// ---------------- SpMM: sup = 0.9*(A_norm h) + 0.1*h0; fp16 gather, fp16 out ----------------
__global__ void spmm_kernel(const __half* __restrict__ hin) {
    int gw = (blockIdx.x * blockDim.x + threadIdx.x) >> 5;
    if (gw >= N_NODES) return;
    int lane = threadIdx.x & 31;
    float dr = g_dinv[gw];
    float sw = 0.9f * dr * dr;

    uint2 selfp = ((const uint2*)(hin + (size_t)gw * NHID))[lane];
    float2 s01 = __half22float2(*(const __half2*)&selfp.x);
    float2 s23 = __half22float2(*(const __half2*)&selfp.y);
    float4 b0 = ((const float4*)(g_h0 + (size_t)gw * NHID))[lane];

    float4 acc;
    acc.x = fmaf(sw, s01.x, 0.1f * b0.x);
    acc.y = fmaf(sw, s01.y, 0.1f * b0.y);
    acc.z = fmaf(sw, s23.x, 0.1f * b0.z);
    acc.w = fmaf(sw, s23.y, 0.1f * b0.w);

    int beg = g_rowptr[gw], end = g_rowptr[gw + 1];
    #pragma unroll 8
    for (int j = beg; j < end; j++) {
        int c = g_ecol[j];
        float w = g_ew[j];
        uint2 vp = ((const uint2*)(hin + (size_t)c * NHID))[lane];
        float2 v01 = __half22float2(*(const __half2*)&vp.x);
        float2 v23 = __half22float2(*(const __half2*)&vp.y);
        acc.x = fmaf(w, v01.x, acc.x);
        acc.y = fmaf(w, v01.y, acc.y);
        acc.z = fmaf(w, v23.x, acc.z);
        acc.w = fmaf(w, v23.y, acc.w);
    }

    ((uint2*)(g_s16 + (size_t)gw * NHID))[lane] =
        make_uint2(pack_f16(acc.x, acc.y), pack_f16(acc.z, acc.w));
}

// ---------------- HMMA fp16 GEMM: C = A @ (Bh+Bl)^T (+bias)(+relu) ----------
// A fp16 [M,K] row-major; B row n holds W[:,n] pre-transposed, fp16 hi/lo.
// CTA 128x128, 8 warps (4x2), warp tile 32x64, BK=64, 2-stage cp.async pipeline.
__global__ __launch_bounds__(256)
void gemm_f16(const __half* __restrict__ A,
              const __half* __restrict__ Bh, const __half* __restrict__ Bl,
              const float* __restrict__ bias,
              float* __restrict__ Cf, __half* __restrict__ C16,
              int M, int K, int do_relu) {
    extern __shared__ char smem[];
    const uint32_t sb = smem_u32(smem);
    const int tid = threadIdx.x;
    const int warp = tid >> 5, lane = tid & 31;
    const int wm = warp & 3, wn = warp >> 2;
    const int row0 = blockIdx.x * BM;

    const int lr = tid >> 1;
    const int lc0 = (tid & 1) * 4;
    const bool avalid = (row0 + lr) < M;
    const size_t arow = avalid ? (size_t)(row0 + lr) : 0;

    float acc[2][8][4];
    #pragma unroll
    for (int m = 0; m < 2; m++)
        #pragma unroll
        for (int j = 0; j < 8; j++)
            #pragma unroll
            for (int q = 0; q < 4; q++) acc[m][j][q] = 0.0f;

    const int nchunk = K / BK;

    auto load_stage = [&](int s, int k0) {
        const uint32_t rbase = sb + s * STAGE_BYTES + lr * 128;
        const __half* pa  = A  + arow * K + k0;
        const __half* pbh = Bh + (size_t)lr * K + k0;
        const __half* pbl = Bl + (size_t)lr * K + k0;
        #pragma unroll
        for (int i = 0; i < 4; i++) {
            int c = lc0 + i;
            uint32_t off = (uint32_t)((c ^ (lr & 7)) << 4);
            cp16(rbase + off,                  pa  + c * 8, avalid);
            cp16(rbase + TILE_BYTES + off,     pbh + c * 8, true);
            cp16(rbase + 2 * TILE_BYTES + off, pbl + c * 8, true);
        }
    };

    load_stage(0, 0);
    cp_commit();

    for (int kc = 0; kc < nchunk; kc++) {
        if (kc + 1 < nchunk) load_stage((kc + 1) & 1, (kc + 1) * BK);
        cp_commit();
        cp_wait1();
        __syncthreads();
        const uint32_t sbase = sb + (kc & 1) * STAGE_BYTES;
        #pragma unroll
        for (int kk = 0; kk < 4; kk++) {
            uint32_t af[2][4];
            #pragma unroll
            for (int m = 0; m < 2; m++) {
                int r = wm * 32 + m * 16 + (lane & 15);
                int cq = kk * 2 + (lane >> 4);
                uint32_t ad = sbase + r * 128 + (uint32_t)((cq ^ (r & 7)) << 4);
                ldsm4(af[m], ad);
            }
            uint32_t bhf[8][2], blf[8][2];
            #pragma unroll
            for (int jp = 0; jp < 4; jp++) {
                int g = lane >> 3;
                int nr = wn * 64 + jp * 16 + ((g >> 1) << 3) + (lane & 7);
                int cq = kk * 2 + (g & 1);
                uint32_t bd = sbase + TILE_BYTES + nr * 128 +
                              (uint32_t)((cq ^ (nr & 7)) << 4);
                uint32_t t[4];
                ldsm4(t, bd);
                bhf[jp * 2][0] = t[0]; bhf[jp * 2][1] = t[1];
                bhf[jp * 2 + 1][0] = t[2]; bhf[jp * 2 + 1][1] = t[3];
                ldsm4(t, bd + TILE_BYTES);
                blf[jp * 2][0] = t[0]; blf[jp * 2][1] = t[1];
                blf[jp * 2 + 1][0] = t[2]; blf[jp * 2 + 1][1] = t[3];
            }
            #pragma unroll
            for (int m = 0; m < 2; m++)
                #pragma unroll
                for (int j = 0; j < 8; j++) {
                    mma16816h(acc[m][j], af[m], bhf[j]);
                    mma16816h(acc[m][j], af[m], blf[j]);
                }
        }
        __syncthreads();
    }

    // epilogue
    #pragma unroll
    for (int m = 0; m < 2; m++) {
        int rbase_ = row0 + wm * 32 + m * 16 + (lane >> 2);
        #pragma unroll
        for (int j = 0; j < 8; j++) {
            int cc = wn * 64 + j * 8 + (lane & 3) * 2;
            float b0v = bias ? bias[cc] : 0.0f;
            float b1v = bias ? bias[cc + 1] : 0.0f;
            float v0 = acc[m][j][0] + b0v, v1 = acc[m][j][1] + b1v;
            float v2 = acc[m][j][2] + b0v, v3 = acc[m][j][3] + b1v;
            if (do_relu) {
                v0 = fmaxf(v0, 0.f); v1 = fmaxf(v1, 0.f);
                v2 = fmaxf(v2, 0.f); v3 = fmaxf(v3, 0.f);
            }
            #pragma unroll
            for (int half_ = 0; half_ < 2; half_++) {
                int r = rbase_ + half_ * 8;
                float va = half_ ? v2 : v0, vb = half_ ? v3 : v1;
                if (r < M) {
                    if (Cf)  *(float2*)(Cf + (size_t)r * 128 + cc) = make_float2(va, vb);
                    if (C16) *(uint32_t*)(C16 + (size_t)r * 128 + cc) = pack_f16(va, vb);
                }
            }
        }
    }
}

// ---------------- launch ----------------
extern "C" void kernel_launch(void* const* d_in, const int* in_sizes, int n_in,
                              void* d_out, int out_size) {
    const float* x      = (const float*)d_in[0];
    const int*   eidx   = (const int*)d_in[1];
    const float* conv_w = (const float*)d_in[2];
    const float* fc0_w  = (const float*)d_in[3];
    const float* fc0_b  = (const float*)d_in[4];
    const float* fc1_w  = (const float*)d_in[5];
    const float* fc1_b  = (const float*)d_in[6];
    float* out = (float*)d_out;
    const int* row = eidx;
    const int* col = eidx + N_EDGES;

    float* h0;
    __half *h16A, *h16B, *s16, *x16, *wth, *wtl, *f0h, *f0l, *f1h, *f1l;
    cudaGetSymbolAddress((void**)&h0,   g_h0);
    cudaGetSymbolAddress((void**)&h16A, g_h16A);
    cudaGetSymbolAddress((void**)&h16B, g_h16B);
    cudaGetSymbolAddress((void**)&s16,  g_s16);
    cudaGetSymbolAddress((void**)&x16,  g_x16);
    cudaGetSymbolAddress((void**)&wth,  g_wth);
    cudaGetSymbolAddress((void**)&wtl,  g_wtl);
    cudaGetSymbolAddress((void**)&f0h,  g_f0h);
    cudaGetSymbolAddress((void**)&f0l,  g_f0l);
    cudaGetSymbolAddress((void**)&f1h,  g_f1h);
    cudaGetSymbolAddress((void**)&f1l,  g_f1l);

    const int SMEM_BYTES = 2 * STAGE_BYTES;  // 96 KB
    static int smem_set = 0;
    if (!smem_set) {
        cudaFuncSetAttribute(gemm_f16, cudaFuncAttributeMaxDynamicSharedMemorySize, SMEM_BYTES);
        smem_set = 1;
    }

    const int NB_N = (N_NODES + 255) / 256;
    const int NB_E = (N_EDGES + 255) / 256;
    const int NB_G = (N_NODES + BM - 1) / BM;   // 391
    const int NB_S = (N_NODES + 1023) / 1024;   // 49

    k_init_nodes<<<NB_N, 256>>>();
    k_count<<<NB_E, 256>>>(row);
    k_dinv<<<NB_N, 256>>>();
    k_scanA<<<NB_S, 1024>>>();
    k_scanB<<<1, 1>>>(NB_S);
    k_scanC<<<NB_N, 256>>>();
    k_fill_csr<<<NB_E, 256>>>(row, col);
    k_wt<<<(NLAYERS * NHID * NHID) / 256, 256>>>(conv_w);
    k_f0t<<<(NHID * NFEAT) / 256, 256>>>(fc0_w);
    k_f1t<<<(NHID * NHID) / 256, 256>>>(fc1_w);
    k_x16<<<(N_NODES * NFEAT / 4 + 255) / 256, 256>>>(x);

    // h0 (fp32 anchor) + h16A (fp16) = relu(x @ fc0_w + fc0_b)
    gemm_f16<<<NB_G, 256, SMEM_BYTES>>>(x16, f0h, f0l, fc0_b,
                                        h0, h16A, N_NODES, NFEAT, 1);

    const __half* hin = h16A;
    for (int l = 0; l < NLAYERS; l++) {
        spmm_kernel<<<(N_NODES * 32 + 255) / 256, 256>>>(hin);
        __half* hout = (l & 1) ? h16A : h16B;
        gemm_f16<<<NB_G, 256, SMEM_BYTES>>>(s16,
                                            wth + (size_t)l * NHID * NHID,
                                            wtl + (size_t)l * NHID * NHID,
                                            nullptr, nullptr, hout,
                                            N_NODES, NHID, 1);
        hin = hout;
    }

    // out = h @ fc1_w + fc1_b
    gemm_f16<<<NB_G, 256, SMEM_BYTES>>>(hin, f1h, f1l, fc1_b,
                                        out, nullptr, N_NODES, NHID, 0);
}